// round 5
// baseline (speedup 1.0000x reference)
#include <cuda_runtime.h>

// Problem constants
#define BB   64      // batch
#define L0   128     // input length
#define C0   16      // input channels
#define L1C  124     // len after block1
#define CH1  128     // channels after block1
#define L2C  120     // len after block2
#define CH2  1024    // channels after block2
#define L3C  116     // len after block3
#define CH3  8192    // channels after block3

#define NSLICE 16
#define LCHUNK 20
#define NLC 6                            // 5x20 + 1x16 = 116
#define ZB  4                            // batch groups of 16
#define CTILES 128                       // 8 channels per tile
#define FUSED_BLOCKS (CTILES * NLC * ZB) // 3072
#define LPAD 24                          // max l-span in smem (LCHUNK+4)

typedef unsigned long long ull;

// Scratch (device globals; no runtime allocation allowed)
__device__ ull   g_out1p[(BB / 2) * L1C * CH1]; // [bpair][l][c1] packed (b even, b odd)
__device__ float g_acc [NSLICE][BB * 2];        // sliced dense accumulators
__device__ unsigned g_count;                    // completed-block counter

// ---------------------------------------------------------------------------
// Packed f32x2 helpers (sm_103a FFMA2 — PTX-only)
__device__ __forceinline__ ull pack2(float lo, float hi) {
    ull d; asm("mov.b64 %0, {%1, %2};" : "=l"(d) : "f"(lo), "f"(hi));
    return d;
}
__device__ __forceinline__ void unpack2(ull d, float& lo, float& hi) {
    asm("mov.b64 {%0, %1}, %2;" : "=f"(lo), "=f"(hi) : "l"(d));
}
__device__ __forceinline__ ull fma2(ull a, ull b, ull c) {
    ull d; asm("fma.rn.f32x2 %0, %1, %2, %3;" : "=l"(d) : "l"(a), "l"(b), "l"(c));
    return d;
}
__device__ __forceinline__ ull relu2(ull x) {
    float lo, hi; unpack2(x, lo, hi);
    return pack2(fmaxf(lo, 0.f), fmaxf(hi, 0.f));
}

// ---------------------------------------------------------------------------
// Block1 (+ zero accumulators/counter). Writes out1 PACKED by batch pair:
// ((float*)g_out1p)[(((b>>1)*L1C + l)*CH1 + o)*2 + (b&1)]
__global__ void block1_kernel(const float* __restrict__ state,
                              const float* __restrict__ k1w,
                              const float* __restrict__ b1) {
    int idx = blockIdx.x * blockDim.x + threadIdx.x;
    if (idx < NSLICE * BB * 2) ((float*)g_acc)[idx] = 0.f;
    if (idx == 0) g_count = 0u;
    if (idx >= BB * L1C * CH1) return;
    int o = idx & (CH1 - 1);
    int l = (idx >> 7) % L1C;
    int b = idx / (L1C * CH1);
    int c = o >> 3;
    const float* sp = state + (b * L0 + l) * C0 + c;
    float v = b1[o];
#pragma unroll
    for (int k = 0; k < 5; k++) v = fmaf(sp[k * C0], k1w[k * CH1 + o], v);
    ((float*)g_out1p)[((size_t)(((b >> 1) * L1C + l) * CH1 + o) << 1) + (b & 1)] =
        fmaxf(v, 0.f);
}

// ---------------------------------------------------------------------------
// Fused block2 + block3 + dense + (last block) finalize.
// Phase 1 (fill): 128 threads compute the packed x2 tile for this block's
//   (8 channels x 8 batch-pairs x l-span) into shared memory once.
// Phase 2 (main): lane = (cl 0..7 channel, fq 0..3 filter-quarter = 2 filters);
//   thread carries 2 packed batch-pairs, rolling x2 window from smem,
//   conv3 via FFMA2, relu + dense scalar, W prefetched one l ahead.
// Warp (8c x 4fq) shfl-reduces; lane 0 atomicAdds into a slice.
// Grid: x = 128 c-tiles, y = 6 l-chunks, z = 4 batch groups; block = 128.
__global__ void __launch_bounds__(128, 5)
fused23_kernel(const float* __restrict__ k2w, const float* __restrict__ b2,
               const float* __restrict__ k3w, const float* __restrict__ b3,
               const float* __restrict__ W,   const float* __restrict__ bd,
               float* __restrict__ out) {
    __shared__ ull x2s[8 * LPAD * 8];   // [bpair][lrel][c]  12.3 KB
    int t  = threadIdx.x;
    int ct = blockIdx.x;                 // c-tile 0..127 (== c1 channel)
    int l0 = blockIdx.y * LCHUNK;
    int l1 = min(L3C, l0 + LCHUNK);
    int zb = blockIdx.z;                 // batch group (16 batches = 8 pairs)

    // ---------------- Phase 1: fill packed x2 tile ----------------
    {
        int fc  = t & 7;                 // channel in tile
        int fbp = (t >> 3) & 7;          // batch pair in group
        int fh2 = t >> 6;                // l-half 0/1
        int span = (l1 - l0) + 4;        // x2 l-range needed
        int half = (span + 1) >> 1;
        int lst  = l0 + fh2 * half;
        int cnt  = min(half, span - fh2 * half);
        int cF   = ct * 8 + fc;          // x2 channel

        ull w2p[5];
#pragma unroll
        for (int k = 0; k < 5; k++) {
            float w = k2w[k * CH2 + cF]; w2p[k] = pack2(w, w);
        }
        float bv = b2[cF];
        ull bias2p = pack2(bv, bv);

        const ull* op = g_out1p + ((size_t)(zb * 8 + fbp) * L1C) * CH1 + ct;
        ull owf[5];
#pragma unroll
        for (int k = 0; k < 5; k++) owf[k] = op[(size_t)(lst + k) * CH1];
        ull* sdst = &x2s[(fbp * LPAD + (lst - l0)) * 8 + fc];
        for (int i = 0; i < cnt; i++) {
            ull v = bias2p;
#pragma unroll
            for (int k = 0; k < 5; k++) v = fma2(owf[k], w2p[k], v);
            sdst[i * 8] = relu2(v);
            if (i + 1 < cnt) {
#pragma unroll
                for (int k = 0; k < 4; k++) owf[k] = owf[k + 1];
                owf[4] = op[(size_t)(lst + i + 5) * CH1];
            }
        }
    }
    __syncthreads();

    // ---------------- Phase 2: conv3 + dense ----------------
    int cl = t & 7;                      // channel lane
    int fq = (t >> 3) & 3;               // filter quarter (filters fq*2, fq*2+1)
    int wg = t >> 5;                     // warp 0..3 -> batches wg*4..wg*4+3
    int c  = ct * 8 + cl;

    // Block3 weights (dup-packed) for the 2 filters
    ull w3p[5][2];
#pragma unroll
    for (int k = 0; k < 5; k++)
#pragma unroll
        for (int j = 0; j < 2; j++) {
            float w = k3w[k * CH3 + c * 8 + fq * 2 + j];
            w3p[k][j] = pack2(w, w);
        }
    ull bias3p[2];
#pragma unroll
    for (int j = 0; j < 2; j++) {
        float bv = b3[c * 8 + fq * 2 + j];
        bias3p[j] = pack2(bv, bv);
    }

    const ull* xs0 = &x2s[((wg * 2 + 0) * LPAD) * 8 + cl];
    const ull* xs1 = &x2s[((wg * 2 + 1) * LPAD) * 8 + cl];

    ull xwp[2][5];
#pragma unroll
    for (int k = 0; k < 5; k++) { xwp[0][k] = xs0[k * 8]; xwp[1][k] = xs1[k * 8]; }

    // Dense W: float4 = (f0c0, f0c1, f1c0, f1c1) at index l*4096 + c*4 + fq
    const float4* Wq = (const float4*)W + ((size_t)c * 4 + fq);
    float4 wf = Wq[(size_t)l0 * 4096];

    float acc[2][2][2] = {};   // [pair][batch-half][col]

#pragma unroll 4
    for (int l = l0; l < l1; l++) {
        float4 wfn;
        bool more = (l + 1 < l1);
        if (more) wfn = Wq[(size_t)(l + 1) * 4096];
#pragma unroll
        for (int p = 0; p < 2; p++) {
            ull v0 = bias3p[0], v1 = bias3p[1];
#pragma unroll
            for (int k = 0; k < 5; k++) {
                v0 = fma2(xwp[p][k], w3p[k][0], v0);
                v1 = fma2(xwp[p][k], w3p[k][1], v1);
            }
            float a, b_, cc, d;
            unpack2(v0, a, b_);
            unpack2(v1, cc, d);
            a  = fmaxf(a, 0.f);  b_ = fmaxf(b_, 0.f);
            cc = fmaxf(cc, 0.f); d  = fmaxf(d, 0.f);
            acc[p][0][0] = fmaf(a,  wf.x, acc[p][0][0]);
            acc[p][0][1] = fmaf(a,  wf.y, acc[p][0][1]);
            acc[p][0][0] = fmaf(cc, wf.z, acc[p][0][0]);
            acc[p][0][1] = fmaf(cc, wf.w, acc[p][0][1]);
            acc[p][1][0] = fmaf(b_, wf.x, acc[p][1][0]);
            acc[p][1][1] = fmaf(b_, wf.y, acc[p][1][1]);
            acc[p][1][0] = fmaf(d,  wf.z, acc[p][1][0]);
            acc[p][1][1] = fmaf(d,  wf.w, acc[p][1][1]);
        }
        if (more) {
            int lrel = l + 5 - l0;
#pragma unroll
            for (int k = 0; k < 4; k++) {
                xwp[0][k] = xwp[0][k + 1];
                xwp[1][k] = xwp[1][k + 1];
            }
            xwp[0][4] = xs0[lrel * 8];
            xwp[1][4] = xs1[lrel * 8];
            wf = wfn;
        }
    }

    // Warp reduction (sums 8 channels x 4 filter-quarters = this tile's share)
    int b0 = zb * 16 + wg * 4;
#pragma unroll
    for (int p = 0; p < 2; p++)
#pragma unroll
        for (int h = 0; h < 2; h++)
#pragma unroll
            for (int col = 0; col < 2; col++) {
                float v = acc[p][h][col];
#pragma unroll
                for (int s = 16; s > 0; s >>= 1)
                    v += __shfl_xor_sync(0xFFFFFFFFu, v, s);
                if ((t & 31) == 0)
                    atomicAdd(&g_acc[ct & (NSLICE - 1)]
                                    [(b0 + 2 * p + h) * 2 + col], v);
            }

    // Last block finalizes (threadfence reduction pattern)
    __shared__ bool s_last;
    __threadfence();
    __syncthreads();
    if (t == 0) s_last = (atomicAdd(&g_count, 1u) == FUSED_BLOCKS - 1u);
    __syncthreads();
    if (s_last) {
        __threadfence();
        int i = t;  // 128 threads == 128 outputs
        volatile float* ga = (volatile float*)g_acc;
        float v = 0.f;
#pragma unroll
        for (int s = 0; s < NSLICE; s++) v += ga[s * BB * 2 + i];
        out[i] = tanhf(v + bd[i & 1]);
    }
}

// ---------------------------------------------------------------------------
extern "C" void kernel_launch(void* const* d_in, const int* in_sizes, int n_in,
                              void* d_out, int out_size) {
    const float* state = (const float*)d_in[0];
    const float* k1w   = (const float*)d_in[1];
    const float* b1    = (const float*)d_in[2];
    const float* k2w   = (const float*)d_in[3];
    const float* b2    = (const float*)d_in[4];
    const float* k3w   = (const float*)d_in[5];
    const float* b3    = (const float*)d_in[6];
    const float* W     = (const float*)d_in[7];
    const float* bd    = (const float*)d_in[8];
    float* out = (float*)d_out;

    block1_kernel<<<(BB * L1C * CH1 + 255) / 256, 256>>>(state, k1w, b1);
    fused23_kernel<<<dim3(CTILES, NLC, ZB), 128>>>(k2w, b2, k3w, b3, W, bd, out);
}

// round 6
// speedup vs baseline: 1.3257x; 1.3257x over previous
#include <cuda_runtime.h>

// Problem constants
#define BB   64      // batch
#define L0   128     // input length
#define C0   16      // input channels
#define L1C  124     // len after block1
#define CH1  128     // channels after block1
#define CH2  1024    // channels after block2
#define L3C  116     // len after block3
#define CH3  8192    // channels after block3

#define NSLICE 16
#define LCHUNK 29
#define NLC 4                            // 4 x 29 = 116 exactly
#define ZB  4                            // batch groups of 16 (8 pairs)
#define CTILES 128                       // 8 channels per tile
#define FUSED_BLOCKS (CTILES * NLC * ZB) // 2048
#define SPAN 33                          // x2 l-span per block = LCHUNK + 4

typedef unsigned long long ull;

// Scratch (device globals; no runtime allocation allowed)
__device__ ull   g_out1p[(BB / 2) * L1C * CH1]; // [bpair][l][c1], packed batches
__device__ float g_acc [NSLICE][BB * 2];        // sliced dense accumulators
__device__ unsigned g_count;                    // completed-block counter

// ---------------------------------------------------------------------------
// Packed f32x2 helpers (sm_103a FFMA2 — PTX-only)
__device__ __forceinline__ ull pack2(float lo, float hi) {
    ull d; asm("mov.b64 %0, {%1, %2};" : "=l"(d) : "f"(lo), "f"(hi));
    return d;
}
__device__ __forceinline__ void unpack2(ull d, float& lo, float& hi) {
    asm("mov.b64 {%0, %1}, %2;" : "=f"(lo), "=f"(hi) : "l"(d));
}
__device__ __forceinline__ ull dup2(float v) {
    ull d; asm("mov.b64 %0, {%1, %1};" : "=l"(d) : "f"(v));
    return d;
}
__device__ __forceinline__ ull fma2(ull a, ull b, ull c) {
    ull d; asm("fma.rn.f32x2 %0, %1, %2, %3;" : "=l"(d) : "l"(a), "l"(b), "l"(c));
    return d;
}
__device__ __forceinline__ ull relu2(ull x) {
    float lo, hi; unpack2(x, lo, hi);
    return pack2(fmaxf(lo, 0.f), fmaxf(hi, 0.f));
}

// ---------------------------------------------------------------------------
// Block1 (+ zero accumulators/counter). out1 packed by batch pair.
__global__ void block1_kernel(const float* __restrict__ state,
                              const float* __restrict__ k1w,
                              const float* __restrict__ b1) {
    int idx = blockIdx.x * blockDim.x + threadIdx.x;
    if (idx < NSLICE * BB * 2) ((float*)g_acc)[idx] = 0.f;
    if (idx == 0) g_count = 0u;
    if (idx >= BB * L1C * CH1) return;
    int o = idx & (CH1 - 1);
    int l = (idx >> 7) % L1C;
    int b = idx / (L1C * CH1);
    int c = o >> 3;
    const float* sp = state + (b * L0 + l) * C0 + c;
    float v = b1[o];
#pragma unroll
    for (int k = 0; k < 5; k++) v = fmaf(sp[k * C0], k1w[k * CH1 + o], v);
    ((float*)g_out1p)[((size_t)(((b >> 1) * L1C + l) * CH1 + o) << 1) + (b & 1)] =
        fmaxf(v, 0.f);
}

// ---------------------------------------------------------------------------
// Fill helper: compute CNT consecutive packed x2 points (rolling out1 window,
// fully unrolled). op points at out1(bpair, lst, c1-channel); dst at the smem
// slot for lrel0.
template <int CNT>
__device__ __forceinline__ void fill_seg(const ull* __restrict__ op,
                                         ull* __restrict__ dst,
                                         const ull w2p[5], ull bias2p) {
    ull w[5];
#pragma unroll
    for (int k = 0; k < 5; k++) w[k] = op[(size_t)k * CH1];
#pragma unroll
    for (int i = 0; i < CNT; i++) {
        ull v = bias2p;
#pragma unroll
        for (int k = 0; k < 5; k++) v = fma2(w[(i + k) % 5], w2p[k], v);
        dst[i * 8] = relu2(v);
        if (i + 1 < CNT) w[i % 5] = op[(size_t)(i + 5) * CH1];
    }
}

// ---------------------------------------------------------------------------
// Fused block2 + block3 + dense + (last block) finalize.
// Phase 1: fill packed x2 tile (8 ch x 8 bpairs x 33 l) into smem.
// Phase 2: lane = (cl 0..7 channel, fq 0..3 -> 2 filters); thread carries 2
// packed batch-pairs; FULLY UNROLLED l-loop with modular register windows
// (zero rotation instructions); conv3 fma2; relu scalar (alu pipe); dense
// col-packed fma2 against W loaded as ull pairs.
__global__ void __launch_bounds__(128, 5)
fused23_kernel(const float* __restrict__ k2w, const float* __restrict__ b2,
               const float* __restrict__ k3w, const float* __restrict__ b3,
               const float* __restrict__ W,   const float* __restrict__ bd,
               float* __restrict__ out) {
    __shared__ ull x2s[8 * SPAN * 8];    // [bpair][lrel][c]  16.9 KB
    int t  = threadIdx.x;
    int ct = blockIdx.x;                 // c-tile == out1 channel c1
    int l0 = blockIdx.y * LCHUNK;
    int zb = blockIdx.z;

    // ---------------- Phase 1: fill ----------------
    {
        int fc  = t & 7;                 // channel in tile
        int fbp = (t >> 3) & 7;          // batch pair in group
        int fh2 = t >> 6;                // warps 0-1: first 17 l, warps 2-3: last 16
        int cF  = ct * 8 + fc;

        ull w2p[5];
#pragma unroll
        for (int k = 0; k < 5; k++) {
            float w = k2w[k * CH2 + cF]; w2p[k] = pack2(w, w);
        }
        float bv = b2[cF];
        ull bias2p = pack2(bv, bv);

        int lst = l0 + fh2 * 17;
        const ull* op = g_out1p + ((size_t)(zb * 8 + fbp) * L1C + lst) * CH1 + ct;
        ull* dst = &x2s[(fbp * SPAN + fh2 * 17) * 8 + fc];
        if (fh2 == 0) fill_seg<17>(op, dst, w2p, bias2p);
        else          fill_seg<16>(op, dst, w2p, bias2p);
    }
    __syncthreads();

    // ---------------- Phase 2: conv3 + dense ----------------
    int cl = t & 7;                      // channel lane
    int fq = (t >> 3) & 3;               // filters fq*2, fq*2+1
    int wg = t >> 5;                     // warp -> batch pairs wg*2, wg*2+1
    int c  = ct * 8 + cl;

    ull w3p[5][2];
#pragma unroll
    for (int k = 0; k < 5; k++)
#pragma unroll
        for (int j = 0; j < 2; j++) {
            float w = k3w[k * CH3 + c * 8 + fq * 2 + j];
            w3p[k][j] = pack2(w, w);
        }
    ull bias3p[2];
#pragma unroll
    for (int j = 0; j < 2; j++) {
        float bv = b3[c * 8 + fq * 2 + j];
        bias3p[j] = pack2(bv, bv);
    }

    const ull* xs0 = &x2s[((wg * 2 + 0) * SPAN) * 8 + cl];
    const ull* xs1 = &x2s[((wg * 2 + 1) * SPAN) * 8 + cl];

    // W as packed col-pairs: ull pair (f0c0|f0c1),(f1c0|f1c1) at
    // ull index (l*4096 + c*4 + fq)*2
    const ull* Wq = (const ull*)W + ((size_t)l0 * 4096 + c * 4 + fq) * 2;

    ull xw0[5], xw1[5];
#pragma unroll
    for (int k = 0; k < 5; k++) { xw0[k] = xs0[k * 8]; xw1[k] = xs1[k * 8]; }

    ull acc[2][2] = {};                  // [pair][batch-half], halves = cols packed

#pragma unroll
    for (int i = 0; i < LCHUNK; i++) {
        ull u0 = Wq[(size_t)i * 8192];       // (f0c0, f0c1)
        ull u1 = Wq[(size_t)i * 8192 + 1];   // (f1c0, f1c1)

        // pair 0
        {
            ull v0 = bias3p[0], v1 = bias3p[1];
#pragma unroll
            for (int k = 0; k < 5; k++) {
                v0 = fma2(xw0[(i + k) % 5], w3p[k][0], v0);
                v1 = fma2(xw0[(i + k) % 5], w3p[k][1], v1);
            }
            float a, b_, e, d;
            unpack2(v0, a, b_); unpack2(v1, e, d);
            a = fmaxf(a, 0.f); b_ = fmaxf(b_, 0.f);
            e = fmaxf(e, 0.f); d  = fmaxf(d, 0.f);
            acc[0][0] = fma2(dup2(a),  u0, acc[0][0]);
            acc[0][0] = fma2(dup2(e),  u1, acc[0][0]);
            acc[0][1] = fma2(dup2(b_), u0, acc[0][1]);
            acc[0][1] = fma2(dup2(d),  u1, acc[0][1]);
        }
        // pair 1
        {
            ull v0 = bias3p[0], v1 = bias3p[1];
#pragma unroll
            for (int k = 0; k < 5; k++) {
                v0 = fma2(xw1[(i + k) % 5], w3p[k][0], v0);
                v1 = fma2(xw1[(i + k) % 5], w3p[k][1], v1);
            }
            float a, b_, e, d;
            unpack2(v0, a, b_); unpack2(v1, e, d);
            a = fmaxf(a, 0.f); b_ = fmaxf(b_, 0.f);
            e = fmaxf(e, 0.f); d  = fmaxf(d, 0.f);
            acc[1][0] = fma2(dup2(a),  u0, acc[1][0]);
            acc[1][0] = fma2(dup2(e),  u1, acc[1][0]);
            acc[1][1] = fma2(dup2(b_), u0, acc[1][1]);
            acc[1][1] = fma2(dup2(d),  u1, acc[1][1]);
        }
        if (i + 1 < LCHUNK) {                // refill oldest slot with lrel i+5
            xw0[i % 5] = xs0[(i + 5) * 8];
            xw1[i % 5] = xs1[(i + 5) * 8];
        }
    }

    // Warp reduction (8 channels x 4 filter-quarters); ull shfl = 2x SHFL.
    int b0 = zb * 16 + wg * 4;
#pragma unroll
    for (int p = 0; p < 2; p++)
#pragma unroll
        for (int h = 0; h < 2; h++) {
            ull v = acc[p][h];
#pragma unroll
            for (int s = 16; s > 0; s >>= 1)
                v = pack2(0.f, 0.f), v = acc[p][h];   // placeholder removed below
        }
    // (real reduction)
#pragma unroll
    for (int p = 0; p < 2; p++)
#pragma unroll
        for (int h = 0; h < 2; h++) {
            float c0, c1_;
            unpack2(acc[p][h], c0, c1_);
#pragma unroll
            for (int s = 16; s > 0; s >>= 1) {
                c0  += __shfl_xor_sync(0xFFFFFFFFu, c0,  s);
                c1_ += __shfl_xor_sync(0xFFFFFFFFu, c1_, s);
            }
            if ((t & 31) == 0) {
                int sl = ct & (NSLICE - 1);
                atomicAdd(&g_acc[sl][(b0 + 2 * p + h) * 2],     c0);
                atomicAdd(&g_acc[sl][(b0 + 2 * p + h) * 2 + 1], c1_);
            }
        }

    // Last block finalizes (threadfence reduction pattern)
    __shared__ bool s_last;
    __threadfence();
    __syncthreads();
    if (t == 0) s_last = (atomicAdd(&g_count, 1u) == FUSED_BLOCKS - 1u);
    __syncthreads();
    if (s_last) {
        __threadfence();
        int i = t;  // 128 threads == 128 outputs
        volatile float* ga = (volatile float*)g_acc;
        float v = 0.f;
#pragma unroll
        for (int s = 0; s < NSLICE; s++) v += ga[s * BB * 2 + i];
        out[i] = tanhf(v + bd[i & 1]);
    }
}

// ---------------------------------------------------------------------------
extern "C" void kernel_launch(void* const* d_in, const int* in_sizes, int n_in,
                              void* d_out, int out_size) {
    const float* state = (const float*)d_in[0];
    const float* k1w   = (const float*)d_in[1];
    const float* b1    = (const float*)d_in[2];
    const float* k2w   = (const float*)d_in[3];
    const float* b2    = (const float*)d_in[4];
    const float* k3w   = (const float*)d_in[5];
    const float* b3    = (const float*)d_in[6];
    const float* W     = (const float*)d_in[7];
    const float* bd    = (const float*)d_in[8];
    float* out = (float*)d_out;

    block1_kernel<<<(BB * L1C * CH1 + 255) / 256, 256>>>(state, k1w, b1);
    fused23_kernel<<<dim3(CTILES, NLC, ZB), 128>>>(k2w, b2, k3w, b3, W, bd, out);
}